// round 13
// baseline (speedup 1.0000x reference)
#include <cuda_runtime.h>
#include <math.h>
#include <stdint.h>

#define BATCH 32
#define SEQ   2048
#define HID   512

typedef unsigned long long ull;

// Scratch (static device globals: allocation-free)
__device__ float g_xproj[SEQ * BATCH * HID];   // [s][b][h] layout
__device__ float g_hfin[BATCH * HID];          // final hidden state

// ---------------------------------------------------------------------------
// packed f32x2 helpers (FFMA2 only reachable via PTX)
// ---------------------------------------------------------------------------
__device__ __forceinline__ void ffma2(ull& acc, ull a, ull b) {
    asm("fma.rn.f32x2 %0, %1, %2, %0;" : "+l"(acc) : "l"(a), "l"(b));
}
__device__ __forceinline__ ull dup2(float v) {
    ull r; asm("mov.b64 %0, {%1, %1};" : "=l"(r) : "f"(v)); return r;
}
__device__ __forceinline__ float2 unpk(ull v) {
    float2 r; asm("mov.b64 {%0, %1}, %2;" : "=f"(r.x), "=f"(r.y) : "l"(v)); return r;
}
// fast tanh: 1 - 2/(e^{2x}+1); saturates to +-1, no NaN path.
__device__ __forceinline__ float ftanh(float x) {
    float e = __expf(x + x);
    return 1.f - __fdividef(2.f, e + 1.f);
}

// ---------------------------------------------------------------------------
// Kernel 1: xproj = x @ W_xh^T + (b_xh + b_hh + b_h), written as [s][b][h]
// (unchanged: 128x128 tile, FFMA2, reg double-buffer)
// ---------------------------------------------------------------------------
__global__ __launch_bounds__(256, 2) void xproj_gemm(
    const float* __restrict__ X,
    const float* __restrict__ Wxh,
    const float* __restrict__ bxh,
    const float* __restrict__ bhh,
    const float* __restrict__ bh)
{
    __shared__ float As[8][128];
    __shared__ float Bs[8][128];
    const int K = HID;
    const int n0 = blockIdx.x * 128;
    const int m0 = blockIdx.y * 128;
    const int tid = threadIdx.x;

    const int lr = tid >> 1;
    const int lc = (tid & 1) << 2;
    const int ca = (tid & 15) << 2;
    const int ra = (tid >> 4) << 2;

    ull acc[8][4];
#pragma unroll
    for (int i = 0; i < 8; i++)
#pragma unroll
        for (int j = 0; j < 4; j++) acc[i][j] = 0ull;

    const float* Aptr = X   + (size_t)(m0 + lr) * K + lc;
    const float* Bptr = Wxh + (size_t)(n0 + lr) * K + lc;

    float4 a4 = *(const float4*)(Aptr);
    float4 b4 = *(const float4*)(Bptr);

    for (int k0 = 0; k0 < K; k0 += 8) {
        As[lc + 0][lr] = a4.x; As[lc + 1][lr] = a4.y;
        As[lc + 2][lr] = a4.z; As[lc + 3][lr] = a4.w;
        Bs[lc + 0][lr] = b4.x; Bs[lc + 1][lr] = b4.y;
        Bs[lc + 2][lr] = b4.z; Bs[lc + 3][lr] = b4.w;
        __syncthreads();
        if (k0 + 8 < K) {
            a4 = *(const float4*)(Aptr + k0 + 8);
            b4 = *(const float4*)(Bptr + k0 + 8);
        }
#pragma unroll
        for (int k = 0; k < 8; k++) {
            float am[8];
            *(float4*)&am[0] = *(const float4*)&As[k][ra];
            *(float4*)&am[4] = *(const float4*)&As[k][ra + 64];
            ulonglong2 b01 = *(const ulonglong2*)&Bs[k][ca];
            ulonglong2 b23 = *(const ulonglong2*)&Bs[k][ca + 64];
#pragma unroll
            for (int i = 0; i < 8; i++) {
                ull ad = dup2(am[i]);
                ffma2(acc[i][0], ad, b01.x);
                ffma2(acc[i][1], ad, b01.y);
                ffma2(acc[i][2], ad, b23.x);
                ffma2(acc[i][3], ad, b23.y);
            }
        }
        __syncthreads();
    }

    float biasv[8];
#pragma unroll
    for (int j = 0; j < 8; j++) {
        int n = n0 + ((j < 4) ? (ca + j) : (64 + ca + j - 4));
        biasv[j] = bxh[n] + bhh[n] + bh[n];
    }

#pragma unroll
    for (int i = 0; i < 8; i++) {
        int m = m0 + ((i < 4) ? (ra + i) : (64 + ra + i - 4));
        int b = m >> 11;
        int s = m & (SEQ - 1);
        float* outr = &g_xproj[((size_t)s * BATCH + b) * HID + n0];
        float2 p0 = unpk(acc[i][0]);
        float2 p1 = unpk(acc[i][1]);
        float2 p2 = unpk(acc[i][2]);
        float2 p3 = unpk(acc[i][3]);
        float4 v0, v1;
        v0.x = p0.x + biasv[0]; v0.y = p0.y + biasv[1];
        v0.z = p1.x + biasv[2]; v0.w = p1.y + biasv[3];
        v1.x = p2.x + biasv[4]; v1.y = p2.y + biasv[5];
        v1.z = p3.x + biasv[6]; v1.w = p3.y + biasv[7];
        *(float4*)&outr[ca]      = v0;
        *(float4*)&outr[64 + ca] = v1;
    }
}

// ---------------------------------------------------------------------------
// Kernel 2: persistent recurrent scan. 16 clusters x 8 CTAs; cluster = 2
// batches, CTA rank = 64 hidden rows. RF weights, fold+butterfly reduce,
// split Lo/Hi consumption. Exchange this round: marshal to LOCAL staging
// (2 STS.128/warp), bar.sync (cheap local drain), then WARP 0 ONLY fans the
// 512B slice out to all 8 peers via raw st.shared::cluster.v4 (lane l ->
// peer l>>2, chunk l&3), each lane finishing with ONE
// mbarrier.arrive.release.cluster (count-16 auto-reset barriers; the release
// orders that lane's own stores — no fences, no bulk engine, no tx arming).
// ---------------------------------------------------------------------------
__global__ __launch_bounds__(512, 1) __cluster_dims__(8, 1, 1)
void scan_kernel(const float* __restrict__ Whh)
{
    __shared__ __align__(16) float hs[2][8][2][64];  // [buf][rank][batch][row] 8KB
    __shared__ __align__(16) float outs[2][2][64];   // [parity][batch][row] 1KB
    __shared__ __align__(8) ull fullmb[2][2];        // [buf][half], count=16

    const int tid = threadIdx.x;
    const int w = tid >> 5, l = tid & 31;

    unsigned rank;
    asm("mov.u32 %0, %%cluster_ctarank;" : "=r"(rank));
    const int b0 = (int)(blockIdx.x >> 3) * 2;
    const int i0 = (int)rank * 64;
    const int myhalf = (rank >= 4) ? 1 : 0;

    // Weights: rows i0+w*4+r, k = c*128 + l*4 + {0..3}, as f32x2 pairs.
    ull wp[4][4][2];
#pragma unroll
    for (int r = 0; r < 4; r++)
#pragma unroll
        for (int c = 0; c < 4; c++) {
            ulonglong2 u = *(const ulonglong2*)
                (&Whh[(size_t)(i0 + w * 4 + r) * HID + c * 128 + l * 4]);
            wp[r][c][0] = u.x; wp[r][c][1] = u.y;
        }

    uint32_t hbase  = (uint32_t)__cvta_generic_to_shared(&hs[0][0][0][0]);
    uint32_t mbbase = (uint32_t)__cvta_generic_to_shared(&fullmb[0][0]);
    // local mbarrier addrs: fullmb[buf][half] = mbbase + buf*16 + half*8

    // warp0 fan-out targets: lane l serves peer p = l>>2, byte chunk (l&3)*128
    // of my 512B slice. rdst = peer p's hs slot for my slice + my chunk.
    uint32_t rdst = 0, rmb = 0;
    if (w == 0) {
        int p = l >> 2;
        uint32_t rb;
        asm("mapa.shared::cluster.u32 %0, %1, %2;" : "=r"(rb) : "r"(hbase), "r"(p));
        rdst = rb + (uint32_t)(rank * 512 + (l & 3) * 128);
        uint32_t rm;
        asm("mapa.shared::cluster.u32 %0, %1, %2;" : "=r"(rm) : "r"(mbbase), "r"(p));
        rmb = rm + (uint32_t)(myhalf * 8);
    }

    // every lane owns (batch brep, row w*4+rrep) after the fold-reduce
    const int brep = (l >> 2) & 1;
    const int rrep = ((l >> 3) & 1) * 2 + ((l >> 4) & 1);

    // Init: h(0)=0 in buf0; mbarriers count=16 (4 producer CTAs x 4 lanes per
    // half), auto-reset each phase.
    for (int i = tid; i < 2 * HID; i += 512) ((float*)hs[0])[i] = 0.f;
    if (tid == 0) {
#pragma unroll
        for (int bfi = 0; bfi < 2; bfi++)
#pragma unroll
            for (int h = 0; h < 2; h++)
                asm volatile("mbarrier.init.shared.b64 [%0], %1;"
                             :: "r"(mbbase + (uint32_t)(bfi * 16 + h * 8)), "r"(16u) : "memory");
    }
    __syncthreads();
    asm volatile("barrier.cluster.arrive.aligned;" ::: "memory");
    asm volatile("barrier.cluster.wait.aligned;" ::: "memory");

    int pb0 = 0, pb1 = 0;   // wait parity per buffer (Lo/Hi flip together)

    // xproj prefetch ring, 2 deep
    const float* xpp = &g_xproj[(size_t)(b0 + brep) * HID + i0 + w * 4 + rrep];
    float xpA = __ldcg(xpp);
    float xpB = __ldcg(xpp + BATCH * HID);
    xpp += 2 * (size_t)BATCH * HID;

    // per-lane base offset into hs slab: h[b][kchunk c] = hb[c*256 + b*64]
    const int lbase = (l >> 4) * 128 + (l & 15) * 4;

    for (int s = 0; s < SEQ; s++) {
        const int cur = s & 1, nxt = cur ^ 1;
        const uint32_t mbLo = mbbase + (uint32_t)(cur * 16);
        const uint32_t mbHi = mbLo + 8u;
        const uint32_t P = (uint32_t)((cur == 0) ? pb0 : pb1);

        // prefetch xp[s+2] BEFORE the waits (hides DRAM latency)
        float xpC = 0.f;
        if (s + 2 < SEQ) { xpC = __ldcg(xpp); xpp += (size_t)BATCH * HID; }

        const float* hb = &hs[cur][0][0][0] + lbase;
        ull acc[2][4];   // [batch][row]
#pragma unroll
        for (int b = 0; b < 2; b++)
#pragma unroll
            for (int r = 0; r < 4; r++) acc[b][r] = 0ull;

        // ---- LOW half: producers 0-3 arrived; compute K in [0,256) ----
        if (s > 0) {
            asm volatile(
                "{\n\t.reg .pred p;\n\t"
                "W%=:\n\t"
                "mbarrier.try_wait.parity.acquire.cluster.shared::cta.b64 p, [%0], %1, 0x989680;\n\t"
                "@!p bra W%=;\n\t}"
                :: "r"(mbLo), "r"(P) : "memory");
        }
#pragma unroll
        for (int b = 0; b < 2; b++) {
#pragma unroll
            for (int c = 0; c < 2; c++) {
                ulonglong2 hc = *(const ulonglong2*)(hb + c * 256 + b * 64);
#pragma unroll
                for (int r = 0; r < 4; r++) {
                    ffma2(acc[b][r], wp[r][c][0], hc.x);
                    ffma2(acc[b][r], wp[r][c][1], hc.y);
                }
            }
        }

        // ---- HIGH half: producers 4-7 arrived; compute K in [256,512) ----
        if (s > 0) {
            asm volatile(
                "{\n\t.reg .pred p;\n\t"
                "W%=:\n\t"
                "mbarrier.try_wait.parity.acquire.cluster.shared::cta.b64 p, [%0], %1, 0x989680;\n\t"
                "@!p bra W%=;\n\t}"
                :: "r"(mbHi), "r"(P) : "memory");
            if (cur == 0) pb0 ^= 1; else pb1 ^= 1;
        }
#pragma unroll
        for (int b = 0; b < 2; b++) {
#pragma unroll
            for (int c = 2; c < 4; c++) {
                ulonglong2 hc = *(const ulonglong2*)(hb + c * 256 + b * 64);
#pragma unroll
                for (int r = 0; r < 4; r++) {
                    ffma2(acc[b][r], wp[r][c][0], hc.x);
                    ffma2(acc[b][r], wp[r][c][1], hc.y);
                }
            }
        }

        float v[8];
#pragma unroll
        for (int b = 0; b < 2; b++)
#pragma unroll
            for (int r = 0; r < 4; r++) {
                float2 u = unpk(acc[b][r]);
                v[b * 4 + r] = u.x + u.y;
            }

        // fold-reduce: 8 values -> 1 per lane (9 shfls)
        {
            const unsigned FM = 0xffffffffu;
            int hi2 = (l >> 2) & 1;
#pragma unroll
            for (int i = 0; i < 4; i++) {
                float send = hi2 ? v[i] : v[i + 4];
                float recv = __shfl_xor_sync(FM, send, 4);
                v[i] = (hi2 ? v[i + 4] : v[i]) + recv;
            }
            int hi3 = (l >> 3) & 1;
#pragma unroll
            for (int i = 0; i < 2; i++) {
                float send = hi3 ? v[i] : v[i + 2];
                float recv = __shfl_xor_sync(FM, send, 8);
                v[i] = (hi3 ? v[i + 2] : v[i]) + recv;
            }
            int hi4 = (l >> 4) & 1;
            {
                float send = hi4 ? v[0] : v[1];
                float recv = __shfl_xor_sync(FM, send, 16);
                v[0] = (hi4 ? v[1] : v[0]) + recv;
            }
            v[0] += __shfl_xor_sync(FM, v[0], 1);
            v[0] += __shfl_xor_sync(FM, v[0], 2);
        }
        float ft = ftanh(v[0] + xpA);

        // marshal rows 0..3 of batch (l&1) into lanes 0/1; 2 STS.128/warp
        // into local parity staging. source lane for (B, r):
        // (B<<2) | ((r>>1)<<3) | ((r&1)<<4)
        {
            const unsigned FM = 0xffffffffu;
            int Bsel = (l & 1) << 2;
            float t0 = __shfl_sync(FM, ft, Bsel);
            float t1 = __shfl_sync(FM, ft, Bsel | 16);
            float t2 = __shfl_sync(FM, ft, Bsel | 8);
            float t3 = __shfl_sync(FM, ft, Bsel | 24);
            if (l < 2)
                *(float4*)&outs[cur][l][w * 4] = make_float4(t0, t1, t2, t3);
        }

        // bar drains only local STS; warp0 fans out + release-arrives.
        asm volatile("bar.sync 0, 512;" ::: "memory");
        if (w == 0) {
            const float4* src = (const float4*)
                ((const char*)&outs[0][0][0] + cur * 512 + (l & 3) * 128);
            const uint32_t dst = rdst + (uint32_t)(nxt * 4096);
#pragma unroll
            for (int i = 0; i < 8; i++) {
                float4 vv = src[i];
                asm volatile("st.shared::cluster.v4.f32 [%0], {%1, %2, %3, %4};"
                             :: "r"(dst + (uint32_t)(i * 16)),
                                "f"(vv.x), "f"(vv.y), "f"(vv.z), "f"(vv.w) : "memory");
            }
            asm volatile("mbarrier.arrive.release.cluster.shared::cluster.b64 _, [%0];"
                         :: "r"(rmb + (uint32_t)(nxt * 16)) : "memory");
        }
        xpA = xpB; xpB = xpC;
    }

    // final: h(SEQ) in hs[0] (SEQ even) under buf0 Lo+Hi
    {
        const uint32_t P = (uint32_t)pb0;
        asm volatile(
            "{\n\t.reg .pred p;\n\t"
            "W%=:\n\t"
            "mbarrier.try_wait.parity.acquire.cluster.shared::cta.b64 p, [%0], %1, 0x989680;\n\t"
            "@!p bra W%=;\n\t}"
            :: "r"(mbbase), "r"(P) : "memory");
        asm volatile(
            "{\n\t.reg .pred p;\n\t"
            "W%=:\n\t"
            "mbarrier.try_wait.parity.acquire.cluster.shared::cta.b64 p, [%0], %1, 0x989680;\n\t"
            "@!p bra W%=;\n\t}"
            :: "r"(mbbase + 8u), "r"(P) : "memory");
    }
    for (int idx = tid; idx < 2 * HID; idx += 512) {
        int b = idx >> 9;
        int k = idx & 511;
        g_hfin[(b0 + b) * HID + k] = hs[0][k >> 6][b][k & 63];
    }
}

// ---------------------------------------------------------------------------
// Kernel 3: out = h_final @ W_fc^T + b_fc.
// ---------------------------------------------------------------------------
__global__ __launch_bounds__(256) void fc_kernel(
    const float* __restrict__ Wfc, const float* __restrict__ bfc,
    float* __restrict__ out)
{
    __shared__ float hsm[HID];
    const int b = blockIdx.x;
    const int o0 = blockIdx.y * 32;
    const int tid = threadIdx.x;
    for (int i = tid; i < HID; i += 256) hsm[i] = g_hfin[b * HID + i];
    __syncthreads();
    const int w = tid >> 5, l = tid & 31;
#pragma unroll
    for (int oi = 0; oi < 4; oi++) {
        int o = o0 + w * 4 + oi;
        const float* wr = Wfc + (size_t)o * HID;
        float sum = 0.f;
#pragma unroll
        for (int j2 = 0; j2 < HID / 32; j2++)
            sum = fmaf(hsm[j2 * 32 + l], wr[j2 * 32 + l], sum);
#pragma unroll
        for (int off = 16; off > 0; off >>= 1)
            sum += __shfl_down_sync(0xffffffffu, sum, off);
        if (l == 0) out[b * HID + o] = sum + bfc[o];
    }
}

// ---------------------------------------------------------------------------
extern "C" void kernel_launch(void* const* d_in, const int* in_sizes, int n_in,
                              void* d_out, int out_size)
{
    const float* x   = (const float*)d_in[0];
    const float* Wxh = (const float*)d_in[1];
    const float* bxh = (const float*)d_in[2];
    const float* Whh = (const float*)d_in[3];
    const float* bhh = (const float*)d_in[4];
    const float* bh  = (const float*)d_in[5];
    const float* Wfc = (const float*)d_in[6];
    const float* bfc = (const float*)d_in[7];
    float* out = (float*)d_out;

    xproj_gemm<<<dim3(HID / 128, (BATCH * SEQ) / 128), 256>>>(x, Wxh, bxh, bhh, bh);
    scan_kernel<<<128, 512>>>(Whh);
    fc_kernel<<<dim3(BATCH, 16), 256>>>(Wfc, bfc, out);
}

// round 14
// speedup vs baseline: 1.6408x; 1.6408x over previous
#include <cuda_runtime.h>
#include <math.h>
#include <stdint.h>

#define BATCH 32
#define SEQ   2048
#define HID   512

typedef unsigned long long ull;

// Scratch (static device globals: allocation-free)
__device__ float g_xproj[SEQ * BATCH * HID];   // [s][b][h] layout
__device__ float g_hfin[BATCH * HID];          // final hidden state

// ---------------------------------------------------------------------------
// packed f32x2 helpers (FFMA2 only reachable via PTX)
// ---------------------------------------------------------------------------
__device__ __forceinline__ void ffma2(ull& acc, ull a, ull b) {
    asm("fma.rn.f32x2 %0, %1, %2, %0;" : "+l"(acc) : "l"(a), "l"(b));
}
__device__ __forceinline__ ull dup2(float v) {
    ull r; asm("mov.b64 %0, {%1, %1};" : "=l"(r) : "f"(v)); return r;
}
__device__ __forceinline__ float2 unpk(ull v) {
    float2 r; asm("mov.b64 {%0, %1}, %2;" : "=f"(r.x), "=f"(r.y) : "l"(v)); return r;
}
// fast tanh: 1 - 2/(e^{2x}+1); saturates to +-1, no NaN path.
__device__ __forceinline__ float ftanh(float x) {
    float e = __expf(x + x);
    return 1.f - __fdividef(2.f, e + 1.f);
}

// ---------------------------------------------------------------------------
// Kernel 1: xproj = x @ W_xh^T + (b_xh + b_hh + b_h), written as [s][b][h]
// (unchanged: 128x128 tile, FFMA2, reg double-buffer)
// ---------------------------------------------------------------------------
__global__ __launch_bounds__(256, 2) void xproj_gemm(
    const float* __restrict__ X,
    const float* __restrict__ Wxh,
    const float* __restrict__ bxh,
    const float* __restrict__ bhh,
    const float* __restrict__ bh)
{
    __shared__ float As[8][128];
    __shared__ float Bs[8][128];
    const int K = HID;
    const int n0 = blockIdx.x * 128;
    const int m0 = blockIdx.y * 128;
    const int tid = threadIdx.x;

    const int lr = tid >> 1;
    const int lc = (tid & 1) << 2;
    const int ca = (tid & 15) << 2;
    const int ra = (tid >> 4) << 2;

    ull acc[8][4];
#pragma unroll
    for (int i = 0; i < 8; i++)
#pragma unroll
        for (int j = 0; j < 4; j++) acc[i][j] = 0ull;

    const float* Aptr = X   + (size_t)(m0 + lr) * K + lc;
    const float* Bptr = Wxh + (size_t)(n0 + lr) * K + lc;

    float4 a4 = *(const float4*)(Aptr);
    float4 b4 = *(const float4*)(Bptr);

    for (int k0 = 0; k0 < K; k0 += 8) {
        As[lc + 0][lr] = a4.x; As[lc + 1][lr] = a4.y;
        As[lc + 2][lr] = a4.z; As[lc + 3][lr] = a4.w;
        Bs[lc + 0][lr] = b4.x; Bs[lc + 1][lr] = b4.y;
        Bs[lc + 2][lr] = b4.z; Bs[lc + 3][lr] = b4.w;
        __syncthreads();
        if (k0 + 8 < K) {
            a4 = *(const float4*)(Aptr + k0 + 8);
            b4 = *(const float4*)(Bptr + k0 + 8);
        }
#pragma unroll
        for (int k = 0; k < 8; k++) {
            float am[8];
            *(float4*)&am[0] = *(const float4*)&As[k][ra];
            *(float4*)&am[4] = *(const float4*)&As[k][ra + 64];
            ulonglong2 b01 = *(const ulonglong2*)&Bs[k][ca];
            ulonglong2 b23 = *(const ulonglong2*)&Bs[k][ca + 64];
#pragma unroll
            for (int i = 0; i < 8; i++) {
                ull ad = dup2(am[i]);
                ffma2(acc[i][0], ad, b01.x);
                ffma2(acc[i][1], ad, b01.y);
                ffma2(acc[i][2], ad, b23.x);
                ffma2(acc[i][3], ad, b23.y);
            }
        }
        __syncthreads();
    }

    float biasv[8];
#pragma unroll
    for (int j = 0; j < 8; j++) {
        int n = n0 + ((j < 4) ? (ca + j) : (64 + ca + j - 4));
        biasv[j] = bxh[n] + bhh[n] + bh[n];
    }

#pragma unroll
    for (int i = 0; i < 8; i++) {
        int m = m0 + ((i < 4) ? (ra + i) : (64 + ra + i - 4));
        int b = m >> 11;
        int s = m & (SEQ - 1);
        float* outr = &g_xproj[((size_t)s * BATCH + b) * HID + n0];
        float2 p0 = unpk(acc[i][0]);
        float2 p1 = unpk(acc[i][1]);
        float2 p2 = unpk(acc[i][2]);
        float2 p3 = unpk(acc[i][3]);
        float4 v0, v1;
        v0.x = p0.x + biasv[0]; v0.y = p0.y + biasv[1];
        v0.z = p1.x + biasv[2]; v0.w = p1.y + biasv[3];
        v1.x = p2.x + biasv[4]; v1.y = p2.y + biasv[5];
        v1.z = p3.x + biasv[6]; v1.w = p3.y + biasv[7];
        *(float4*)&outr[ca]      = v0;
        *(float4*)&outr[64 + ca] = v1;
    }
}

// ---------------------------------------------------------------------------
// Kernel 2: persistent recurrent scan. 16 clusters x 8 CTAs; cluster = 2
// batches, CTA rank = 64 hidden rows. RF weights, fold+butterfly reduce.
// h layout [buf][rank][batch][64]. QUARTER-split delivery: quarter q covers
// ranks {2q,2q+1}; per-buffer mbarrier per quarter (expect 1024B, or 512B
// for my own quarter — my slice arrives by local STS). Consumer pipeline:
// wait q0 -> compute K[0,128) -> wait q1 -> ... (arrival skew overlaps
// compute). Producer: rep lanes STS into local hs[nxt][rank]; 7 remote 512B
// bulk copies credit each peer's quarter-(rank>>1) barrier. (R9 + 4-way.)
// ---------------------------------------------------------------------------
__global__ __launch_bounds__(512, 1) __cluster_dims__(8, 1, 1)
void scan_kernel(const float* __restrict__ Whh)
{
    __shared__ __align__(16) float hs[2][8][2][64];  // [buf][rank][batch][row] 8KB
    __shared__ __align__(8) ull fullmb[2][4];        // [buf][quarter]

    const int tid = threadIdx.x;
    const int w = tid >> 5, l = tid & 31;

    unsigned rank;
    asm("mov.u32 %0, %%cluster_ctarank;" : "=r"(rank));
    const int b0 = (int)(blockIdx.x >> 3) * 2;
    const int i0 = (int)rank * 64;
    const int myq = (int)(rank >> 1);               // my quarter

    // Weights: rows i0+w*4+r, k = c*128 + l*4 + {0..3}, as f32x2 pairs.
    ull wp[4][4][2];
#pragma unroll
    for (int r = 0; r < 4; r++)
#pragma unroll
        for (int c = 0; c < 4; c++) {
            ulonglong2 u = *(const ulonglong2*)
                (&Whh[(size_t)(i0 + w * 4 + r) * HID + c * 128 + l * 4]);
            wp[r][c][0] = u.x; wp[r][c][1] = u.y;
        }

    uint32_t hbase  = (uint32_t)__cvta_generic_to_shared(&hs[0][0][0][0]);
    uint32_t mbbase = (uint32_t)__cvta_generic_to_shared(&fullmb[0][0]);
    // local mbarrier addrs: fullmb[buf][q] = mbbase + buf*32 + q*8
    // expect per quarter: 2 producers x 512B, minus my own 512B (self by STS)
    uint32_t expQ[4];
#pragma unroll
    for (int q = 0; q < 4; q++) expQ[q] = (q == myq) ? 512u : 1024u;

    // warp0 lanes 0-7 (l != rank): peer l's hs slot for MY slice + peer l's
    // quarter-(myq) mbarrier.
    uint32_t rdst = 0, rmb = 0;
    if (w == 0 && l < 8) {
        uint32_t myslice = hbase + (uint32_t)(rank * 512);
        asm("mapa.shared::cluster.u32 %0, %1, %2;" : "=r"(rdst) : "r"(myslice), "r"(l));
        asm("mapa.shared::cluster.u32 %0, %1, %2;" : "=r"(rmb)  : "r"(mbbase), "r"(l));
        rmb += (uint32_t)(myq * 8);
    }

    // rep lanes (l%4==0) own (batch brep, row w*4+rrep) after the fold-reduce
    const int brep = (l >> 2) & 1;
    const int rrep = ((l >> 3) & 1) * 2 + ((l >> 4) & 1);
    const bool isrep = ((l & 3) == 0);
    // self-STS address for rep lane: hs[nxt][rank][brep][w*4+rrep]
    float* selfp = &hs[0][rank][brep][w * 4 + rrep];

    // Init: h(0)=0; mbarriers count=1; pre-arm buf1 (targets of s=0 copies).
    for (int i = tid; i < 2 * HID; i += 512) ((float*)hs[0])[i] = 0.f;
    if (tid == 0) {
#pragma unroll
        for (int bfi = 0; bfi < 2; bfi++)
#pragma unroll
            for (int q = 0; q < 4; q++)
                asm volatile("mbarrier.init.shared.b64 [%0], %1;"
                             :: "r"(mbbase + (uint32_t)(bfi * 32 + q * 8)), "r"(1u) : "memory");
#pragma unroll
        for (int q = 0; q < 4; q++)
            asm volatile("mbarrier.arrive.expect_tx.shared::cta.b64 _, [%0], %1;"
                         :: "r"(mbbase + (uint32_t)(32 + q * 8)), "r"(expQ[q]) : "memory");
    }
    __syncthreads();
    asm volatile("barrier.cluster.arrive.aligned;" ::: "memory");
    asm volatile("barrier.cluster.wait.aligned;" ::: "memory");

    int pb0 = 0, pb1 = 0;   // wait parity per buffer (quarters flip together)

    // xproj prefetch ring, 2 deep, on rep lanes
    const float* xpp = &g_xproj[(size_t)(b0 + brep) * HID + i0 + w * 4 + rrep];
    float xpA = 0.f, xpB = 0.f;
    if (isrep) {
        xpA = __ldcg(xpp);
        xpB = __ldcg(xpp + BATCH * HID);
        xpp += 2 * (size_t)BATCH * HID;
    }

    // per-lane base offset into hs slab: h[b][kchunk c] = hb[c*256 + b*64]
    const int lbase = (l >> 4) * 128 + (l & 15) * 4;

    for (int s = 0; s < SEQ; s++) {
        const int cur = s & 1, nxt = cur ^ 1;
        const uint32_t mbQ = mbbase + (uint32_t)(cur * 32);
        const uint32_t P = (uint32_t)((cur == 0) ? pb0 : pb1);

        // prefetch xp[s+2] BEFORE the waits (hides DRAM latency)
        float xpC = 0.f;
        if (isrep && s + 2 < SEQ) { xpC = __ldcg(xpp); xpp += (size_t)BATCH * HID; }

        const float* hb = &hs[cur][0][0][0] + lbase;
        ull acc[2][4];   // [batch][row]
#pragma unroll
        for (int b = 0; b < 2; b++)
#pragma unroll
            for (int r = 0; r < 4; r++) acc[b][r] = 0ull;

        // ---- quarter pipeline: wait q -> arm q -> compute K chunk q ----
#pragma unroll
        for (int q = 0; q < 4; q++) {
            const uint32_t mb = mbQ + (uint32_t)(q * 8);
            if (s > 0) {
                asm volatile(
                    "{\n\t.reg .pred p;\n\t"
                    "W%=:\n\t"
                    "mbarrier.try_wait.parity.acquire.cta.shared::cta.b64 p, [%0], %1, 0x989680;\n\t"
                    "@!p bra W%=;\n\t}"
                    :: "r"(mb), "r"(P) : "memory");
            }
            if (tid == 0)
                asm volatile("mbarrier.arrive.expect_tx.shared::cta.b64 _, [%0], %1;"
                             :: "r"(mb), "r"(expQ[q]) : "memory");
#pragma unroll
            for (int b = 0; b < 2; b++) {
                ulonglong2 hc = *(const ulonglong2*)(hb + q * 256 + b * 64);
#pragma unroll
                for (int r = 0; r < 4; r++) {
                    ffma2(acc[b][r], wp[r][q][0], hc.x);
                    ffma2(acc[b][r], wp[r][q][1], hc.y);
                }
            }
        }
        if (s > 0) { if (cur == 0) pb0 ^= 1; else pb1 ^= 1; }

        float v[8];
#pragma unroll
        for (int b = 0; b < 2; b++)
#pragma unroll
            for (int r = 0; r < 4; r++) {
                float2 u = unpk(acc[b][r]);
                v[b * 4 + r] = u.x + u.y;
            }

        // fold-reduce: 8 values -> 1 per lane (9 shfls total)
        {
            const unsigned FM = 0xffffffffu;
            int hi2 = (l >> 2) & 1;
#pragma unroll
            for (int i = 0; i < 4; i++) {
                float send = hi2 ? v[i] : v[i + 4];
                float recv = __shfl_xor_sync(FM, send, 4);
                v[i] = (hi2 ? v[i + 4] : v[i]) + recv;
            }
            int hi3 = (l >> 3) & 1;
#pragma unroll
            for (int i = 0; i < 2; i++) {
                float send = hi3 ? v[i] : v[i + 2];
                float recv = __shfl_xor_sync(FM, send, 8);
                v[i] = (hi3 ? v[i + 2] : v[i]) + recv;
            }
            int hi4 = (l >> 4) & 1;
            {
                float send = hi4 ? v[0] : v[1];
                float recv = __shfl_xor_sync(FM, send, 16);
                v[0] = (hi4 ? v[1] : v[0]) + recv;
            }
            v[0] += __shfl_xor_sync(FM, v[0], 1);
            v[0] += __shfl_xor_sync(FM, v[0], 2);
        }
        // rep lanes finish output; STS directly into local hs[nxt][rank]
        if (isrep)
            selfp[nxt * 1024] = ftanh(v[0] + xpA);   // 1024 floats = buf stride
        __syncthreads();

        // warp0 lanes 0-7 (skip self): one 512B bulk copy to peer l,
        // crediting peer's quarter-(myq) barrier for buffer nxt.
        if (w == 0 && l < 8 && l != (int)rank) {
            asm volatile("fence.proxy.async.shared::cta;" ::: "memory");
            asm volatile(
                "cp.async.bulk.shared::cluster.shared::cta.mbarrier::complete_tx::bytes"
                " [%0], [%1], %2, [%3];"
                :: "r"(rdst + (uint32_t)(nxt * 4096)),
                   "r"(hbase + (uint32_t)(nxt * 4096 + rank * 512)),
                   "r"(512u),
                   "r"(rmb + (uint32_t)(nxt * 32))
                : "memory");
        }
        xpA = xpB; xpB = xpC;
    }

    // final: h(SEQ) lands in hs[0] (SEQ even) under buf0 quarters 0-3
    {
        const uint32_t P = (uint32_t)pb0;
#pragma unroll
        for (int q = 0; q < 4; q++) {
            asm volatile(
                "{\n\t.reg .pred p;\n\t"
                "W%=:\n\t"
                "mbarrier.try_wait.parity.acquire.cta.shared::cta.b64 p, [%0], %1, 0x989680;\n\t"
                "@!p bra W%=;\n\t}"
                :: "r"(mbbase + (uint32_t)(q * 8)), "r"(P) : "memory");
        }
    }
    for (int idx = tid; idx < 2 * HID; idx += 512) {
        int b = idx >> 9;
        int k = idx & 511;
        g_hfin[(b0 + b) * HID + k] = hs[0][k >> 6][b][k & 63];
    }
}

// ---------------------------------------------------------------------------
// Kernel 3: out = h_final @ W_fc^T + b_fc.
// ---------------------------------------------------------------------------
__global__ __launch_bounds__(256) void fc_kernel(
    const float* __restrict__ Wfc, const float* __restrict__ bfc,
    float* __restrict__ out)
{
    __shared__ float hsm[HID];
    const int b = blockIdx.x;
    const int o0 = blockIdx.y * 32;
    const int tid = threadIdx.x;
    for (int i = tid; i < HID; i += 256) hsm[i] = g_hfin[b * HID + i];
    __syncthreads();
    const int w = tid >> 5, l = tid & 31;
#pragma unroll
    for (int oi = 0; oi < 4; oi++) {
        int o = o0 + w * 4 + oi;
        const float* wr = Wfc + (size_t)o * HID;
        float sum = 0.f;
#pragma unroll
        for (int j2 = 0; j2 < HID / 32; j2++)
            sum = fmaf(hsm[j2 * 32 + l], wr[j2 * 32 + l], sum);
#pragma unroll
        for (int off = 16; off > 0; off >>= 1)
            sum += __shfl_down_sync(0xffffffffu, sum, off);
        if (l == 0) out[b * HID + o] = sum + bfc[o];
    }
}

// ---------------------------------------------------------------------------
extern "C" void kernel_launch(void* const* d_in, const int* in_sizes, int n_in,
                              void* d_out, int out_size)
{
    const float* x   = (const float*)d_in[0];
    const float* Wxh = (const float*)d_in[1];
    const float* bxh = (const float*)d_in[2];
    const float* Whh = (const float*)d_in[3];
    const float* bhh = (const float*)d_in[4];
    const float* bh  = (const float*)d_in[5];
    const float* Wfc = (const float*)d_in[6];
    const float* bfc = (const float*)d_in[7];
    float* out = (float*)d_out;

    xproj_gemm<<<dim3(HID / 128, (BATCH * SEQ) / 128), 256>>>(x, Wxh, bxh, bhh, bh);
    scan_kernel<<<128, 512>>>(Whh);
    fc_kernel<<<dim3(BATCH, 16), 256>>>(Wfc, bfc, out);
}